// round 3
// baseline (speedup 1.0000x reference)
#include <cuda_runtime.h>
#include <math.h>

#define BB  64
#define HH  2048
#define GG  8192
#define CCC 512
#define RRR 100

// ---- device scratch (no allocations allowed) ----
__device__ float g_h1[BB*HH];
__device__ float g_h [BB*HH];
__device__ float g_pre[BB*GG];
__device__ float g_mask[BB*GG];
__device__ float g_S[BB];
__device__ float g_sparse[BB*GG];
__device__ float g_state[BB*CCC];
__device__ float g_sep[BB*CCC];
__device__ float g_comp[BB*CCC];
__device__ float g_rec[BB*CCC];
__device__ float g_itch[BB*256];
__device__ float g_ic[BB];
__device__ float g_weffT[CCC*CCC];
__device__ float g_oh[BB*HH];
__device__ float g_ps[1<<21];   // split-K partials (8 MB)

// ---- threefry2x32, JAX partitionable scheme: per-element counter (0, idx),
// output = x0 ^ x1, uniform via mantissa bits, keep if u > 0.1 ----
__device__ __forceinline__ unsigned tf_rotl(unsigned x, int d){ return (x<<d)|(x>>(32-d)); }
__device__ __forceinline__ bool tf_keep(int idx){
    const unsigned ks0=0u, ks1=42u, ks2=0x1BD11BDAu^0u^42u;
    unsigned x0 = 0u + ks0;              // counts_hi = 0 (idx < 2^32)
    unsigned x1 = (unsigned)idx + ks1;   // counts_lo = idx
#define TFR(r) { x0+=x1; x1=tf_rotl(x1,(r)); x1^=x0; }
    TFR(13) TFR(15) TFR(26) TFR(6)  x0+=ks1; x1+=ks2+1u;
    TFR(17) TFR(29) TFR(16) TFR(24) x0+=ks2; x1+=ks0+2u;
    TFR(13) TFR(15) TFR(26) TFR(6)  x0+=ks0; x1+=ks1+3u;
    TFR(17) TFR(29) TFR(16) TFR(24) x0+=ks1; x1+=ks2+4u;
    TFR(13) TFR(15) TFR(26) TFR(6)  x0+=ks2; x1+=ks0+5u;
#undef TFR
    unsigned bits = x0 ^ x1;
    float u = __uint_as_float((bits>>9)|0x3f800000u) - 1.0f;
    return u > 0.1f;
}

// ---- split-K GEMM: partial[b,n] = sum_{k in segment} X[b,k]*W[n,k] ----
// 64x64 tile, 256 threads, 4x4 micro-tile, register double-buffered.
__global__ __launch_bounds__(256) void gemm64(
    const float* __restrict__ Xg, const float* __restrict__ Wg,
    float* __restrict__ ps, int K, int Kc, int N, int wzStride)
{
    __shared__ float Xs[32][68];
    __shared__ float Ws[32][68];
    const int tid = threadIdx.x;
    const int n0  = blockIdx.x * 64;
    const int kb  = blockIdx.y * Kc;
    const float* W = Wg + (size_t)blockIdx.z * (size_t)wzStride;
    float* outp = ps + (size_t)(blockIdx.z*gridDim.y + blockIdx.y) * (size_t)(BB*N);

    const int ty = tid >> 4, tx = tid & 15;
    const int row0 = tid >> 3,         quad0 = tid & 7;
    const int row1 = (tid+256) >> 3,   quad1 = tid & 7;

    float acc[4][4];
#pragma unroll
    for (int i=0;i<4;i++)
#pragma unroll
        for (int j=0;j<4;j++) acc[i][j]=0.0f;

    float4 xr0 = *(const float4*)(Xg + (size_t)row0*K + kb + quad0*4);
    float4 wr0 = *(const float4*)(W  + (size_t)(n0+row0)*K + kb + quad0*4);
    float4 xr1 = *(const float4*)(Xg + (size_t)row1*K + kb + quad1*4);
    float4 wr1 = *(const float4*)(W  + (size_t)(n0+row1)*K + kb + quad1*4);

    for (int k0 = kb; k0 < kb + Kc; k0 += 32) {
        Xs[quad0*4+0][row0]=xr0.x; Xs[quad0*4+1][row0]=xr0.y; Xs[quad0*4+2][row0]=xr0.z; Xs[quad0*4+3][row0]=xr0.w;
        Ws[quad0*4+0][row0]=wr0.x; Ws[quad0*4+1][row0]=wr0.y; Ws[quad0*4+2][row0]=wr0.z; Ws[quad0*4+3][row0]=wr0.w;
        Xs[quad1*4+0][row1]=xr1.x; Xs[quad1*4+1][row1]=xr1.y; Xs[quad1*4+2][row1]=xr1.z; Xs[quad1*4+3][row1]=xr1.w;
        Ws[quad1*4+0][row1]=wr1.x; Ws[quad1*4+1][row1]=wr1.y; Ws[quad1*4+2][row1]=wr1.z; Ws[quad1*4+3][row1]=wr1.w;
        __syncthreads();

        int kn = k0 + 32;
        if (kn < kb + Kc) {
            xr0 = *(const float4*)(Xg + (size_t)row0*K + kn + quad0*4);
            wr0 = *(const float4*)(W  + (size_t)(n0+row0)*K + kn + quad0*4);
            xr1 = *(const float4*)(Xg + (size_t)row1*K + kn + quad1*4);
            wr1 = *(const float4*)(W  + (size_t)(n0+row1)*K + kn + quad1*4);
        }
#pragma unroll
        for (int kk=0;kk<32;kk++){
            float4 a = *(const float4*)&Xs[kk][ty*4];
            float4 b = *(const float4*)&Ws[kk][tx*4];
            acc[0][0]+=a.x*b.x; acc[0][1]+=a.x*b.y; acc[0][2]+=a.x*b.z; acc[0][3]+=a.x*b.w;
            acc[1][0]+=a.y*b.x; acc[1][1]+=a.y*b.y; acc[1][2]+=a.y*b.z; acc[1][3]+=a.y*b.w;
            acc[2][0]+=a.z*b.x; acc[2][1]+=a.z*b.y; acc[2][2]+=a.z*b.z; acc[2][3]+=a.z*b.w;
            acc[3][0]+=a.w*b.x; acc[3][1]+=a.w*b.y; acc[3][2]+=a.w*b.z; acc[3][3]+=a.w*b.w;
        }
        __syncthreads();
    }
#pragma unroll
    for (int i=0;i<4;i++){
        float4 v = make_float4(acc[i][0],acc[i][1],acc[i][2],acc[i][3]);
        *(float4*)(outp + (size_t)(ty*4+i)*N + n0 + tx*4) = v;
    }
}

// ---- split-K reduce + epilogue ----
#define M_NONE 0
#define M_RELU 1
#define M_MASK 2
#define M_MF   3
#define M_RECB 4
__global__ void combine_k(const float* __restrict__ ps, int KS, int BN, int N,
                          const float* __restrict__ bias, const float* __restrict__ extra,
                          float* __restrict__ out, int mode)
{
    int idx = blockIdx.x*256 + threadIdx.x;
    if (idx >= BN) return;
    float z = 0.0f;
    for (int s=0;s<KS;s++) z += ps[(size_t)s*BN + idx];
    int n = idx % N;
    float v;
    if (mode == M_RECB) { z += extra[idx]; v = fmaxf(z,0.0f); }
    else {
        if (bias) z += bias[n];
        if (mode==M_NONE)      v = z;
        else if (mode==M_RELU) v = fmaxf(z,0.0f);
        else if (mode==M_MASK) { float g = 1.0f/(1.0f+expf(-z)); v = (g>0.1f)?1.0f:0.0f; }
        else { float p = z*extra[n]; v = tf_keep(idx)?p:0.0f; }   // M_MF
    }
    out[idx] = v;
}

// 3-branch running pairwise average: sig=0 -> tanh*0.8, sig=1 -> sigmoid*0.6
__global__ void combine3_k(const float* __restrict__ ps, int KS,
                           const float* __restrict__ bias, float* __restrict__ out, int sig)
{
    int idx = blockIdx.x*256 + threadIdx.x;
    if (idx >= BB*CCC) return;
    int n = idx & (CCC-1);
    float z[3];
#pragma unroll
    for (int br=0;br<3;br++){
        float a = 0.0f;
        for (int s=0;s<KS;s++) a += ps[(size_t)(br*KS+s)*(BB*CCC) + idx];
        z[br] = a + bias[br*CCC + n];
    }
    float v;
    if (!sig){
        v = tanhf(z[0])*0.8f;
        v = (v + tanhf(z[1])*0.8f)*0.5f;
        v = (v + tanhf(z[2])*0.8f)*0.5f;
    } else {
        v = 0.6f/(1.0f+expf(-z[0]));
        v = (v + 0.6f/(1.0f+expf(-z[1])))*0.5f;
        v = (v + 0.6f/(1.0f+expf(-z[2])))*0.5f;
    }
    out[idx] = v;
}

__global__ void mask_stats_k()
{
    __shared__ float red[256];
    int b = blockIdx.x, tid = threadIdx.x;
    float s = 0.0f;
    for (int j=tid;j<GG;j+=256) s += g_mask[(size_t)b*GG + j];
    red[tid]=s; __syncthreads();
    for (int off=128;off;off>>=1){ if(tid<off) red[tid]+=red[tid+off]; __syncthreads(); }
    if (tid==0) g_S[b]=red[0];
}

// inhibition + sparse + LayerNorm; one block per batch row
__global__ void sparse_ln_k(const float* __restrict__ lng, const float* __restrict__ lnb)
{
    __shared__ float sv[GG];
    __shared__ float red[256];
    int b = blockIdx.x, tid = threadIdx.x;
    float tot = 0.0f;
    for (int i=0;i<BB;i++) tot += g_S[i];
    bool anyb = tot > 0.0f;
    float Sb = g_S[b];

    float lsum = 0.0f;
    for (int j=tid;j<GG;j+=256){
        float m = g_mask[(size_t)b*GG + j];
        float p = g_pre [(size_t)b*GG + j];
        if (anyb) p -= 0.1f*(Sb - m);
        float s = p*m;
        sv[j]=s; lsum+=s;
    }
    red[tid]=lsum; __syncthreads();
    for (int off=128;off;off>>=1){ if(tid<off) red[tid]+=red[tid+off]; __syncthreads(); }
    float mu = red[0]/(float)GG; __syncthreads();

    float lsq = 0.0f;
    for (int j=tid;j<GG;j+=256){ float d=sv[j]-mu; lsq+=d*d; }
    red[tid]=lsq; __syncthreads();
    for (int off=128;off;off>>=1){ if(tid<off) red[tid]+=red[tid+off]; __syncthreads(); }
    float rstd = 1.0f/sqrtf(red[0]/(float)GG + 1e-5f);

    for (int j=tid;j<GG;j+=256)
        g_sparse[(size_t)b*GG + j] = (sv[j]-mu)*rstd*lng[j] + lnb[j];
}

// WeffT[h,d] = sum_c strength_c * recW[c,d,h]
__global__ void build_weff_k(const float* __restrict__ recW)
{
    int gid = blockIdx.x*256 + threadIdx.x;
    if (gid >= CCC*CCC) return;
    int d = gid >> 9, h = gid & (CCC-1);
    float acc = 0.0f;
    for (int c=0;c<RRR;c++)
        acc += (1.0f/(1.0f+0.1f*(float)c)) * recW[(size_t)c*CCC*CCC + gid];
    g_weffT[(size_t)h*CCC + d] = acc;
}

__global__ void itc2_k(const float* __restrict__ w2, const float* __restrict__ b2)
{
    __shared__ float red[256];
    int b = blockIdx.x, tid = threadIdx.x;
    red[tid] = g_itch[b*256+tid]*w2[tid]; __syncthreads();
    for (int off=128;off;off>>=1){ if(tid<off) red[tid]+=red[tid+off]; __syncthreads(); }
    if (tid==0) g_ic[b] = 1.0f/(1.0f+expf(-(red[0]+b2[0])));
}

__global__ void update_k()
{
    int idx = blockIdx.x*256 + threadIdx.x;
    if (idx >= BB*CCC) return;
    float ic = g_ic[idx>>9];
    g_state[idx] = (1.0f-ic)*g_state[idx] + ic*g_rec[idx];
}

extern "C" void kernel_launch(void* const* d_in, const int* in_sizes, int n_in,
                              void* d_out, int out_size)
{
    const float* x1    = (const float*)d_in[0];
    const float* ipW1  = (const float*)d_in[1];
    const float* ipb1  = (const float*)d_in[2];
    const float* ipW2  = (const float*)d_in[3];
    const float* ipb2  = (const float*)d_in[4];
    const float* encW  = (const float*)d_in[5];
    const float* encb  = (const float*)d_in[6];
    const float* gateW = (const float*)d_in[7];
    const float* gateb = (const float*)d_in[8];
    const float* ln_g  = (const float*)d_in[9];
    const float* ln_b  = (const float*)d_in[10];
    /* d_in[11] lateral: ones-eye, handled analytically */
    const float* mfW   = (const float*)d_in[12];
    const float* mfb   = (const float*)d_in[13];
    const float* mf_cs = (const float*)d_in[14];
    const float* recW  = (const float*)d_in[15];
    const float* recb  = (const float*)d_in[16];
    const float* sepW  = (const float*)d_in[17];
    const float* sepb  = (const float*)d_in[18];
    const float* compW = (const float*)d_in[19];
    const float* compb = (const float*)d_in[20];
    const float* itcW1 = (const float*)d_in[21];
    const float* itcb1 = (const float*)d_in[22];
    const float* itcW2 = (const float*)d_in[23];
    const float* itcb2 = (const float*)d_in[24];
    const float* opW1  = (const float*)d_in[25];
    const float* opb1  = (const float*)d_in[26];
    const float* opW2  = (const float*)d_in[27];
    const float* opb2  = (const float*)d_in[28];

    float *p_h1,*p_h,*p_pre,*p_mask,*p_sparse,*p_state,*p_sep,*p_comp,*p_rec,*p_itch,*p_weffT,*p_oh,*p_ps;
    cudaGetSymbolAddress((void**)&p_h1, g_h1);
    cudaGetSymbolAddress((void**)&p_h,  g_h);
    cudaGetSymbolAddress((void**)&p_pre, g_pre);
    cudaGetSymbolAddress((void**)&p_mask, g_mask);
    cudaGetSymbolAddress((void**)&p_sparse, g_sparse);
    cudaGetSymbolAddress((void**)&p_state, g_state);
    cudaGetSymbolAddress((void**)&p_sep, g_sep);
    cudaGetSymbolAddress((void**)&p_comp, g_comp);
    cudaGetSymbolAddress((void**)&p_rec, g_rec);
    cudaGetSymbolAddress((void**)&p_itch, g_itch);
    cudaGetSymbolAddress((void**)&p_weffT, g_weffT);
    cudaGetSymbolAddress((void**)&p_oh, g_oh);
    cudaGetSymbolAddress((void**)&p_ps, g_ps);

    dim3 t(256);

    // Weff (used in all 3 iterations)
    build_weff_k<<<1024, t>>>(recW);

    // input projection
    gemm64<<<dim3(32,8,1), t>>>(x1,  ipW1, p_ps, 1024, 128, 2048, 0);
    combine_k<<<512, t>>>(p_ps, 8, BB*2048, 2048, ipb1, nullptr, p_h1, M_RELU);
    gemm64<<<dim3(32,8,1), t>>>(p_h1, ipW2, p_ps, 2048, 256, 2048, 0);
    combine_k<<<512, t>>>(p_ps, 8, BB*2048, 2048, ipb2, nullptr, p_h, M_NONE);

    // granule: pre + gate mask
    gemm64<<<dim3(128,2,1), t>>>(p_h, encW, p_ps, 2048, 1024, 8192, 0);
    combine_k<<<2048, t>>>(p_ps, 2, BB*8192, 8192, encb, nullptr, p_pre, M_NONE);
    gemm64<<<dim3(128,2,1), t>>>(p_pre, gateW, p_ps, 8192, 4096, 8192, 0);
    combine_k<<<2048, t>>>(p_ps, 2, BB*8192, 8192, gateb, nullptr, p_mask, M_MASK);

    // inhibition + sparse + LN
    mask_stats_k<<<64, t>>>();
    sparse_ln_k<<<64, t>>>(ln_g, ln_b);

    // mossy fiber + dropout
    gemm64<<<dim3(8,16,1), t>>>(p_sparse, mfW, p_ps, 8192, 512, 512, 0);
    combine_k<<<128, t>>>(p_ps, 16, BB*512, 512, mfb, mf_cs, p_state, M_MF);

    // CA3 recurrence, 3 iterations
    for (int it=0; it<3; it++) {
        gemm64<<<dim3(8,4,3), t>>>(p_state, sepW, p_ps, 512, 128, 512, CCC*CCC);
        combine3_k<<<128, t>>>(p_ps, 4, sepb, p_sep, 0);
        gemm64<<<dim3(8,4,3), t>>>(p_sep, compW, p_ps, 512, 128, 512, CCC*CCC);
        combine3_k<<<128, t>>>(p_ps, 4, compb, p_comp, 1);
        gemm64<<<dim3(8,8,1), t>>>(p_comp, p_weffT, p_ps, 512, 64, 512, 0);
        combine_k<<<128, t>>>(p_ps, 8, BB*512, 512, nullptr, recb, p_rec, M_RECB);
        gemm64<<<dim3(4,8,1), t>>>(p_rec, itcW1, p_ps, 512, 64, 256, 0);
        combine_k<<<64, t>>>(p_ps, 8, BB*256, 256, itcb1, nullptr, p_itch, M_RELU);
        itc2_k<<<64, t>>>(itcW2, itcb2);
        update_k<<<128, t>>>();
    }

    // output projection
    gemm64<<<dim3(32,4,1), t>>>(p_state, opW1, p_ps, 512, 128, 2048, 0);
    combine_k<<<512, t>>>(p_ps, 4, BB*2048, 2048, opb1, nullptr, p_oh, M_RELU);
    gemm64<<<dim3(16,8,1), t>>>(p_oh, opW2, p_ps, 2048, 256, 1024, 0);
    combine_k<<<256, t>>>(p_ps, 8, BB*1024, 1024, opb2, nullptr, (float*)d_out, M_NONE);
}